// round 7
// baseline (speedup 1.0000x reference)
#include <cuda_runtime.h>
#include <cstdint>

// ---------------- tile / pipeline config ----------------
#define CTA_M    128
#define CTA_N    128          // 96 cols via IMMA warps + 32 cols via dp4a warps
#define N_IMMA   96
#define K_STAGE  128
#define STAGES   3
#define CTA_THREADS 192       // warps 0-3: IMMA, warps 4-5: dp4a + producer

#define A_BYTES      (CTA_M * K_STAGE)                 // 16384
#define STAGE_BYTES  ((CTA_M + CTA_N) * K_STAGE)       // 32768
#define SMEM_TOTAL   (STAGES * STAGE_BYTES)            // 98304 (dynamic)

#define MAXM 8192
#define MAXN 4096
#define MAXK 4096

__device__ __align__(16) int8_t g_X8[(size_t)MAXM * MAXK];   // 32 MB
__device__ __align__(16) int8_t g_W8[(size_t)MAXN * MAXK];   // 16 MB
__device__ int g_mode;   // 0 = raw int8, 1 = int32-promoted, 2 = float32-promoted

// ---------------- PTX helpers ----------------
__device__ __forceinline__ uint32_t smem_u32(const void* p) {
    uint32_t a;
    asm("{ .reg .u64 t; cvta.to.shared.u64 t, %1; cvt.u32.u64 %0, t; }"
        : "=r"(a) : "l"(p));
    return a;
}
__device__ __forceinline__ uint32_t sw128(uint32_t o) { return o ^ ((o >> 3) & 0x70); }

__device__ __forceinline__ void cp16(uint32_t dst, const void* src) {
    asm volatile("cp.async.cg.shared.global [%0], [%1], 16;"
                 :: "r"(dst), "l"(src) : "memory");
}
__device__ __forceinline__ void ldsm_x4(uint32_t* r, uint32_t addr) {
    asm volatile("ldmatrix.sync.aligned.m8n8.x4.shared.b16 {%0,%1,%2,%3}, [%4];"
                 : "=r"(r[0]), "=r"(r[1]), "=r"(r[2]), "=r"(r[3])
                 : "r"(addr));
}
__device__ __forceinline__ void mma_s8(int* c, const uint32_t* a, const uint32_t* b) {
    asm volatile(
        "mma.sync.aligned.m16n8k32.row.col.s32.s8.s8.s32 "
        "{%0,%1,%2,%3}, {%4,%5,%6,%7}, {%8,%9}, {%0,%1,%2,%3};"
        : "+r"(c[0]), "+r"(c[1]), "+r"(c[2]), "+r"(c[3])
        : "r"(a[0]), "r"(a[1]), "r"(a[2]), "r"(a[3]),
          "r"(b[0]), "r"(b[1]));
}
__device__ __forceinline__ int dp4a(int a, int b, int c) {
    int d;
    asm("dp4a.s32.s32 %0, %1, %2, %3;" : "=r"(d) : "r"(a), "r"(b), "r"(c));
    return d;
}

// ---- mbarrier ring helpers ----
__device__ __forceinline__ void mbar_init(uint32_t mbar, uint32_t cnt) {
    asm volatile("mbarrier.init.shared.b64 [%0], %1;" :: "r"(mbar), "r"(cnt) : "memory");
}
__device__ __forceinline__ void mbar_arrive(uint32_t mbar) {
    asm volatile("mbarrier.arrive.shared.b64 _, [%0];" :: "r"(mbar) : "memory");
}
__device__ __forceinline__ void cp_arrive_noinc(uint32_t mbar) {
    asm volatile("cp.async.mbarrier.arrive.noinc.shared::cta.b64 [%0];"
                 :: "r"(mbar) : "memory");
}
__device__ __forceinline__ void mbar_wait(uint32_t mbar, uint32_t parity) {
    uint32_t done;
    asm volatile("{\n\t.reg .pred p;\n\t"
                 "mbarrier.try_wait.parity.acquire.cta.shared::cta.b64 p, [%1], %2;\n\t"
                 "selp.b32 %0, 1, 0, p;\n\t}"
                 : "=r"(done) : "r"(mbar), "r"(parity) : "memory");
    while (!done) {
        asm volatile("{\n\t.reg .pred p;\n\t"
                     "mbarrier.try_wait.parity.acquire.cta.shared::cta.b64 p, [%1], %2, 0x989680;\n\t"
                     "selp.b32 %0, 1, 0, p;\n\t}"
                     : "=r"(done) : "r"(mbar), "r"(parity) : "memory");
    }
}

// ---------------- dtype detection ----------------
__global__ void detect_kernel(const void* __restrict__ x, long n_elems) {
    __shared__ int s_i32ok, s_f32ok;
    if (threadIdx.x == 0) { s_i32ok = 1; s_f32ok = 1; }
    __syncthreads();
    const int*   xi = (const int*)x;
    const float* xf = (const float*)x;
    const long max_words = n_elems / 4;
    const long stride = max_words / (256 * 64);
    int i32ok = 1, f32ok = 1;
    for (int j = 0; j < 64; j++) {
        long idx = ((long)threadIdx.x * 64 + j) * stride;
        int w = xi[idx];
        i32ok &= (w >= -128 && w <= 127);
        float f = xf[idx];
        f32ok &= (f == rintf(f)) && (fabsf(f) <= 127.0f);
    }
    if (!i32ok) atomicAnd(&s_i32ok, 0);
    if (!f32ok) atomicAnd(&s_f32ok, 0);
    __syncthreads();
    if (threadIdx.x == 0) g_mode = s_i32ok ? 1 : (s_f32ok ? 2 : 0);
}

// ---------------- convert: promoted input -> packed int8 ----------------
__global__ void convert_kernel(const void* __restrict__ src, int8_t* __restrict__ dst,
                               long n) {
    const int mode = g_mode;
    const long stride = (long)gridDim.x * blockDim.x * 16;
    for (long i = ((long)blockIdx.x * blockDim.x + threadIdx.x) * 16; i < n; i += stride) {
        int4 out;
        if (mode == 1) {
            const int4* s = (const int4*)((const int*)src + i);
            int4 v0 = s[0], v1 = s[1], v2 = s[2], v3 = s[3];
            out.x = (v0.x & 0xFF) | ((v0.y & 0xFF) << 8) | ((v0.z & 0xFF) << 16) | ((v0.w & 0xFF) << 24);
            out.y = (v1.x & 0xFF) | ((v1.y & 0xFF) << 8) | ((v1.z & 0xFF) << 16) | ((v1.w & 0xFF) << 24);
            out.z = (v2.x & 0xFF) | ((v2.y & 0xFF) << 8) | ((v2.z & 0xFF) << 16) | ((v2.w & 0xFF) << 24);
            out.w = (v3.x & 0xFF) | ((v3.y & 0xFF) << 8) | ((v3.z & 0xFF) << 16) | ((v3.w & 0xFF) << 24);
        } else if (mode == 2) {
            const float4* s = (const float4*)((const float*)src + i);
            float4 v0 = s[0], v1 = s[1], v2 = s[2], v3 = s[3];
            int4 a0 = make_int4(__float2int_rn(v0.x), __float2int_rn(v0.y),
                                __float2int_rn(v0.z), __float2int_rn(v0.w));
            int4 a1 = make_int4(__float2int_rn(v1.x), __float2int_rn(v1.y),
                                __float2int_rn(v1.z), __float2int_rn(v1.w));
            int4 a2 = make_int4(__float2int_rn(v2.x), __float2int_rn(v2.y),
                                __float2int_rn(v2.z), __float2int_rn(v2.w));
            int4 a3 = make_int4(__float2int_rn(v3.x), __float2int_rn(v3.y),
                                __float2int_rn(v3.z), __float2int_rn(v3.w));
            out.x = (a0.x & 0xFF) | ((a0.y & 0xFF) << 8) | ((a0.z & 0xFF) << 16) | ((a0.w & 0xFF) << 24);
            out.y = (a1.x & 0xFF) | ((a1.y & 0xFF) << 8) | ((a1.z & 0xFF) << 16) | ((a1.w & 0xFF) << 24);
            out.z = (a2.x & 0xFF) | ((a2.y & 0xFF) << 8) | ((a2.z & 0xFF) << 16) | ((a2.w & 0xFF) << 24);
            out.w = (a3.x & 0xFF) | ((a3.y & 0xFF) << 8) | ((a3.z & 0xFF) << 16) | ((a3.w & 0xFF) << 24);
        } else {
            out = *(const int4*)((const int8_t*)src + i);
        }
        *(int4*)(dst + i) = out;
    }
}

__device__ __forceinline__ float bias_at(const void* BIAS, int idx, int mode) {
    if (mode == 1) return (float)((const int*)BIAS)[idx];
    if (mode == 2) return ((const float*)BIAS)[idx];
    return (float)((const int8_t*)BIAS)[idx];
}

// producer (dp4a warps only, 64 threads): 32 x 16B chunks per thread per stage.
__device__ __forceinline__ void produce_stage64(uint32_t base, const int8_t* xs,
                                                const int8_t* ws, int t2, int K) {
#pragma unroll
    for (int i = 0; i < 16; i++)
        cp16(base + sw128(((uint32_t)t2 + 64u * i) * 16), xs + (size_t)i * 8 * K);
#pragma unroll
    for (int i = 0; i < 16; i++)
        cp16(base + A_BYTES + sw128(((uint32_t)t2 + 64u * i) * 16), ws + (size_t)i * 8 * K);
}

// ---------------- warp-specialized hybrid GEMM with mbarrier ring ----------------
// Warps 0-3 (IMMA): pure LDSM+MMA stream over cols [0,96).
// Warps 4-5 (dp4a): all cp.async production + dp4a GEMM over cols [96,128).
// full[s]: 64 producer-thread cp.async arrivals. empty[s]: 6 per-warp arrivals.
// Consumers free-run up to STAGES-1 stages ahead; no __syncthreads in mainloop.
__global__ void __launch_bounds__(CTA_THREADS, 2)
w8a8_linear_kernel(const int8_t* __restrict__ X, const int8_t* __restrict__ W,
                   const void* __restrict__ BIAS, const float* __restrict__ pA,
                   const float* __restrict__ pB, float* __restrict__ OUT,
                   int M, int N, int K)
{
    extern __shared__ char smem[];
    __shared__ __align__(8) unsigned long long mbar_store[2 * STAGES];
    const uint32_t sb = smem_u32(smem);
    const uint32_t mb = smem_u32(mbar_store);        // full[s]=mb+8s, empty[s]=mb+8(STAGES+s)
    const int tid  = threadIdx.x;
    const int wid  = tid >> 5;
    const int lane = tid & 31;
    const bool isdp = (wid >= 4);

    const int m_base = blockIdx.y * CTA_M;
    const int n_base = blockIdx.x * CTA_N;
    const int num_k  = K / K_STAGE;

    if (tid == 0) {
#pragma unroll
        for (int s = 0; s < STAGES; s++) {
            mbar_init(mb + 8 * s, 64);                   // full: producer threads
            mbar_init(mb + 8 * (STAGES + s), 6);         // empty: consumer warps
        }
    }
    __syncthreads();

    const float alpha = *pA;
    const float beta  = *pB;
    const int   mode  = g_mode;

    if (!isdp) {
        // ================= IMMA warps =================
        const int warpM = wid >> 1;
        const int warpN = wid & 1;
        const int arow_l = (lane & 7) + ((lane >> 3) & 1) * 8;
        const int aoff_l = (lane >> 4) * 16;
        const int brow_l = (lane >> 4) * 8 + (lane & 7);
        const int boff_l = ((lane >> 3) & 1) * 16;

        int acc[4][6][4];
#pragma unroll
        for (int mi = 0; mi < 4; mi++)
#pragma unroll
            for (int ni = 0; ni < 6; ni++)
#pragma unroll
                for (int e = 0; e < 4; e++) acc[mi][ni][e] = 0;

        int buf = 0, cph = 0;
        for (int ki = 0; ki < num_k; ki++) {
            mbar_wait(mb + 8 * buf, cph);                // stage resident
            const uint32_t SA = sb + buf * STAGE_BYTES;
            const uint32_t SB = SA + A_BYTES;
#pragma unroll
            for (int j = 0; j < 4; j++) {                // 4 x k32 steps
                uint32_t af[4][4], bf[3][4];
#pragma unroll
                for (int mi = 0; mi < 4; mi++)
                    ldsm_x4(af[mi], SA + sw128((uint32_t)(warpM * 64 + mi * 16 + arow_l) * 128
                                               + j * 32 + aoff_l));
#pragma unroll
                for (int pi = 0; pi < 3; pi++)
                    ldsm_x4(bf[pi], SB + sw128((uint32_t)(warpN * 48 + pi * 16 + brow_l) * 128
                                               + j * 32 + boff_l));
#pragma unroll
                for (int mi = 0; mi < 4; mi++)
#pragma unroll
                    for (int pi = 0; pi < 3; pi++) {
                        mma_s8(acc[mi][2 * pi],     af[mi], &bf[pi][0]);
                        mma_s8(acc[mi][2 * pi + 1], af[mi], &bf[pi][2]);
                    }
            }
            __syncwarp();
            if (lane == 0) mbar_arrive(mb + 8 * (STAGES + buf));   // release stage
            if (++buf == STAGES) { buf = 0; cph ^= 1; }
        }

        // epilogue: cols [0, 96)
#pragma unroll
        for (int mi = 0; mi < 4; mi++) {
#pragma unroll
            for (int ni = 0; ni < 6; ni++) {
                const int row0 = m_base + warpM * 64 + mi * 16 + (lane >> 2);
                const int col0 = n_base + warpN * 48 + ni * 8 + (lane & 3) * 2;
                const float bb0 = beta * bias_at(BIAS, col0, mode);
                const float bb1 = beta * bias_at(BIAS, col0 + 1, mode);
#pragma unroll
                for (int h = 0; h < 2; h++) {
                    const int row = row0 + h * 8;
                    int q0 = __float2int_rn(fmaf(alpha, (float)acc[mi][ni][2 * h],     bb0));
                    int q1 = __float2int_rn(fmaf(alpha, (float)acc[mi][ni][2 * h + 1], bb1));
                    q0 = max(-128, min(127, q0));
                    q1 = max(-128, min(127, q1));
                    *reinterpret_cast<float2*>(OUT + (size_t)row * N + col0) =
                        make_float2((float)q0, (float)q1);
                }
            }
        }
    } else {
        // ============ dp4a warps: producer + fma-pipe GEMM ============
        const int t2 = tid - 128;
        const int8_t* xsrc = X + (size_t)(m_base + (t2 >> 3)) * K + (t2 & 7) * 16;
        const int8_t* wsrc = W + (size_t)(n_base + (t2 >> 3)) * K + (t2 & 7) * 16;

        const int dwid = wid - 4;
        const int tm = lane >> 2;
        const int tn = lane & 3;
        const int rbase = dwid * 64 + tm;

        int acc[8][8];
#pragma unroll
        for (int i = 0; i < 8; i++)
#pragma unroll
            for (int j = 0; j < 8; j++) acc[i][j] = 0;

        // producer cursor (empty-wait starts at parity 1: fresh barriers pass)
        int ws = 0, wph = 1;
        // prologue: fill STAGES-1 stages
#pragma unroll
        for (int s = 0; s < STAGES - 1; s++) {
            produce_stage64(sb + ws * STAGE_BYTES, xsrc + (size_t)s * K_STAGE,
                            wsrc + (size_t)s * K_STAGE, t2, K);
            cp_arrive_noinc(mb + 8 * ws);
            if (++ws == STAGES) { ws = 0; wph ^= 1; }
        }

        int buf = 0, cph = 0;
        for (int ki = 0; ki < num_k; ki++) {
            // produce stage ki+STAGES-1
            if (ki + STAGES - 1 < num_k) {
                mbar_wait(mb + 8 * (STAGES + ws), wph);  // stage free
                produce_stage64(sb + ws * STAGE_BYTES,
                                xsrc + (size_t)(ki + STAGES - 1) * K_STAGE,
                                wsrc + (size_t)(ki + STAGES - 1) * K_STAGE, t2, K);
                cp_arrive_noinc(mb + 8 * ws);
                if (++ws == STAGES) { ws = 0; wph ^= 1; }
            }
            // consume stage buf
            mbar_wait(mb + 8 * buf, cph);
            const char* SAc = smem + buf * STAGE_BYTES;
            const char* SBc = SAc + A_BYTES;
#pragma unroll
            for (int kk = 0; kk < 8; kk++) {
                int4 av[8];
#pragma unroll
                for (int i = 0; i < 8; i++)
                    av[i] = *reinterpret_cast<const int4*>(
                        SAc + sw128((uint32_t)(rbase + 8 * i) * 128 + kk * 16));
#pragma unroll
                for (int jj = 0; jj < 8; jj++) {
                    const int4 bv = *reinterpret_cast<const int4*>(
                        SBc + sw128((uint32_t)(N_IMMA + tn + 4 * jj) * 128 + kk * 16));
#pragma unroll
                    for (int i = 0; i < 8; i++) {
                        int c = acc[i][jj];
                        c = dp4a(av[i].x, bv.x, c);
                        c = dp4a(av[i].y, bv.y, c);
                        c = dp4a(av[i].z, bv.z, c);
                        c = dp4a(av[i].w, bv.w, c);
                        acc[i][jj] = c;
                    }
                }
            }
            __syncwarp();
            if (lane == 0) mbar_arrive(mb + 8 * (STAGES + buf));
            if (++buf == STAGES) { buf = 0; cph ^= 1; }
        }

        // epilogue: cols [96, 128)
#pragma unroll
        for (int jj = 0; jj < 8; jj++) {
            const int col = n_base + N_IMMA + tn + 4 * jj;
            const float bb = beta * bias_at(BIAS, col, mode);
#pragma unroll
            for (int i = 0; i < 8; i++) {
                const int row = m_base + rbase + 8 * i;
                int q = __float2int_rn(fmaf(alpha, (float)acc[i][jj], bb));
                q = max(-128, min(127, q));
                OUT[(size_t)row * N + col] = (float)q;
            }
        }
    }
}

// ---------------- launch ----------------
extern "C" void kernel_launch(void* const* d_in, const int* in_sizes, int n_in,
                              void* d_out, int out_size)
{
    const void*  x    = d_in[0];
    const void*  w    = d_in[1];
    const void*  bias = d_in[2];
    const float* a    = (const float*)d_in[3];
    const float* b    = (const float*)d_in[4];

    const int N = in_sizes[2];              // 4096
    const int K = in_sizes[1] / N;          // 4096
    const int M = in_sizes[0] / K;          // 8192

    int8_t *x8, *w8;
    cudaGetSymbolAddress((void**)&x8, g_X8);
    cudaGetSymbolAddress((void**)&w8, g_W8);

    detect_kernel<<<1, 256>>>(x, (long)in_sizes[0]);
    convert_kernel<<<4096, 256>>>(x, x8, (long)M * K);
    convert_kernel<<<4096, 256>>>(w, w8, (long)N * K);

    cudaFuncSetAttribute(w8a8_linear_kernel,
                         cudaFuncAttributeMaxDynamicSharedMemorySize, SMEM_TOTAL);
    dim3 grid(N / CTA_N, M / CTA_M);        // (32, 64)
    w8a8_linear_kernel<<<grid, CTA_THREADS, SMEM_TOTAL>>>(
        x8, w8, bias, a, b, (float*)d_out, M, N, K);
}